// round 10
// baseline (speedup 1.0000x reference)
#include <cuda_runtime.h>

#define LVLS 16
#define TSIZE 16384
#define NPTS 262144
#define TMASK 16383
#define PRIME1 (-1640531535)   // 2654435761 wrapped to int32
#define PRIME2 (805459861)
#define CTAS_PER_LVL 9
#define NTHREADS 1024
#define GRIDSZ (CTAS_PER_LVL * LVLS)   // 144 CTAs = one wave, all co-resident
#define TPTS 256                        // points per transpose tile
#define NTILES (NPTS / TPTS)            // 1024
#define TPITCH (TPTS + 2)               // float2 pitch: 258 -> 2064B rows (16B aligned)

// Scratch in (L, N) layout of float2 — 33.5MB static device array (allowed).
__device__ float2 g_scr[(size_t)LVLS * NPTS];
// Monotonic grid-barrier counter (never reset; target derived from old value,
// so it is correct across the correctness run, capture, and every replay).
__device__ unsigned long long g_arrive;

// ---------------------------------------------------------------------------
// Fused kernel.
// Phase 1: hash-grid gather, one CTA per (level, slice), 128KB level table in
//          shared memory, coalesced float2 scratch stores in (L,N,2) layout.
// Barrier: software grid barrier (safe: 144 CTAs at 1 CTA/SM = single wave).
// Phase 2: (L,N,2) -> (N,L*2) transpose at FULL residency (144 x 1024), smem
//          reused as tile buffer. No second launch, no ramp, no L1D flush.
// ---------------------------------------------------------------------------
__global__ __launch_bounds__(NTHREADS, 1)
void hash_enc_fused(const float* __restrict__ x,
                    const float* __restrict__ emb,
                    float* __restrict__ out)
{
    extern __shared__ float2 smem[];   // phase 1: table (128KB); phase 2: tile
    const int level = blockIdx.y;
    const int bid   = blockIdx.y * CTAS_PER_LVL + blockIdx.x;   // 0..143
    const int t     = threadIdx.x;

    // ---------------- Phase 1: gather ----------------
    {
        const float4* src = (const float4*)(emb + (size_t)level * TSIZE * 2);
        float4* dst = (float4*)smem;
        #pragma unroll
        for (int i = t; i < (TSIZE * 2) / 4; i += NTHREADS)
            dst[i] = src[i];
    }
    __syncthreads();

    // Per-level resolution (identical formula — index math must not change)
    const float bgrow = expf((logf(512.0f) - logf(16.0f)) * (1.0f / 16.0f));
    const float scale = 16.0f * powf(bgrow, (float)level);

    float2* scr = g_scr + (size_t)level * NPTS;

    const int stride = CTAS_PER_LVL * NTHREADS;
    for (int n = blockIdx.x * NTHREADS + t; n < NPTS; n += stride) {
        const float x0 = x[n * 3 + 0];
        const float x1 = x[n * 3 + 1];
        const float x2 = x[n * 3 + 2];

        const float u0 = x0 * scale, u1 = x1 * scale, u2 = x2 * scale;
        const float f0 = floorf(u0), f1 = floorf(u1), f2 = floorf(u2);
        const int   i0 = (int)f0,    i1 = (int)f1,    i2 = (int)f2;
        const float d0 = u0 - f0, d1 = u1 - f1, d2 = u2 - f2;
        const float o0 = 1.0f - d0, o1 = 1.0f - d1, o2 = 1.0f - d2;

        const int pl0 = i0;                  const int ph0 = pl0 + 1;
        const int pl1 = i1 * PRIME1;         const int ph1 = pl1 + PRIME1;
        const int pl2 = i2 * PRIME2;         const int ph2 = pl2 + PRIME2;
        // frac==0 corners carry an exactly-zero weight, so hi = lo+1 is safe.

        float ax = 0.0f, ay = 0.0f;
        #pragma unroll
        for (int k = 0; k < 8; ++k) {
            const int a = (k >> 2) & 1;
            const int b = (k >> 1) & 1;
            const int c = k & 1;
            const int h = (a ? ph0 : pl0) ^ (b ? ph1 : pl1) ^ (c ? ph2 : pl2);
            const int idx = h & TMASK;
            const float w = (a ? d0 : o0) * (b ? d1 : o1) * (c ? d2 : o2);
            const float2 v = smem[idx];
            ax = fmaf(w, v.x, ax);
            ay = fmaf(w, v.y, ay);
        }
        scr[n] = make_float2(ax, ay);   // coalesced 256B warp store
    }

    // ---------------- Grid barrier ----------------
    __syncthreads();
    if (t == 0) {
        __threadfence();                                   // release scratch
        const unsigned long long old = atomicAdd(&g_arrive, 1ULL);
        const unsigned long long target = (old / GRIDSZ + 1ULL) * GRIDSZ;
        volatile unsigned long long* p = &g_arrive;
        while (*p < target) { }
        __threadfence();                                   // acquire
    }
    __syncthreads();

    // ---------------- Phase 2: transpose ----------------
    float2 (*tile)[TPITCH] = (float2 (*)[TPITCH])smem;     // 16x258x8B = 33KB
    const float4* scr4 = (const float4*)g_scr;
    float4* out4 = (float4*)out;

    for (int tl = bid; tl < NTILES; tl += GRIDSZ) {
        const int n0 = tl * TPTS;

        // Load: 2 passes; warp reads 512B contiguous per level row; STS.128
        // contiguous (conflict-free). __ldcg: L2-resident scratch, skip L1.
        #pragma unroll
        for (int pass = 0; pass < 2; ++pass) {
            const int l    = pass * 8 + (t >> 7);
            const int slot = t & 127;
            const float4 v = __ldcg(scr4 + (size_t)l * (NPTS / 2) + (n0 >> 1) + slot);
            *(float4*)&tile[l][2 * slot] = v;
        }
        __syncthreads();

        // Store: warp writes 4 consecutive full 128B output rows per pass.
        const int q  = t & 7;          // float4 slot within output row
        const int pr = t >> 3;         // 0..127
        #pragma unroll
        for (int i = 0; i < 2; ++i) {
            const int p = i * 128 + pr;
            const float2 a = tile[2 * q][p];
            const float2 b = tile[2 * q + 1][p];
            out4[(size_t)(n0 + p) * (LVLS / 2) + q] = make_float4(a.x, a.y, b.x, b.y);
        }
        __syncthreads();               // tile reused next iteration
    }
}

extern "C" void kernel_launch(void* const* d_in, const int* in_sizes, int n_in,
                              void* d_out, int out_size)
{
    const float* x;
    const float* emb;
    if (in_sizes[0] == NPTS * 3) {
        x = (const float*)d_in[0];
        emb = (const float*)d_in[1];
    } else {
        x = (const float*)d_in[1];
        emb = (const float*)d_in[0];
    }
    float* out = (float*)d_out;

    cudaFuncSetAttribute(hash_enc_fused,
                         cudaFuncAttributeMaxDynamicSharedMemorySize,
                         TSIZE * 2 * (int)sizeof(float));

    dim3 grid(CTAS_PER_LVL, LVLS);   // 144 CTAs = one full wave @ 1 CTA/SM
    hash_enc_fused<<<grid, NTHREADS, TSIZE * 2 * sizeof(float)>>>(x, emb, out);
}